// round 2
// baseline (speedup 1.0000x reference)
#include <cuda_runtime.h>
#include <math.h>

#define HX_B 16
#define HX_C 256
#define HX_H 128
#define HX_W 128
#define HX_HW (HX_H * HX_W)      // 16384
#define HX_HW4 (HX_HW / 4)       // 4096

// scratch (device globals: allocation-free per harness rules)
__device__ float g_avg[HX_B * HX_HW];   // 1 MiB
__device__ float g_max[HX_B * HX_HW];   // 1 MiB
__device__ float g_sig[HX_B * HX_HW];   // 1 MiB

// ---------------------------------------------------------------------------
// Kernel 1: per-(b,h,w) mean & max over C=256. One thread per float4 of hw.
// Coalesced: consecutive threads -> consecutive w. 256 strided float4 loads.
// ---------------------------------------------------------------------------
__global__ void __launch_bounds__(256) reduce_kernel(const float4* __restrict__ x4) {
    int i = blockIdx.x * blockDim.x + threadIdx.x;   // over B*HW4 = 65536
    if (i >= HX_B * HX_HW4) return;
    int b   = i / HX_HW4;
    int hw4 = i - b * HX_HW4;
    const float4* p = x4 + (size_t)b * HX_C * HX_HW4 + hw4;

    float sx = 0.f, sy = 0.f, sz = 0.f, sw = 0.f;
    float mx = -INFINITY, my = -INFINITY, mz = -INFINITY, mw = -INFINITY;
    #pragma unroll 8
    for (int c = 0; c < HX_C; c++) {
        float4 v = p[(size_t)c * HX_HW4];
        sx += v.x; sy += v.y; sz += v.z; sw += v.w;
        mx = fmaxf(mx, v.x); my = fmaxf(my, v.y);
        mz = fmaxf(mz, v.z); mw = fmaxf(mw, v.w);
    }
    const float inv = 1.0f / HX_C;
    float4 a4 = make_float4(sx * inv, sy * inv, sz * inv, sw * inv);
    float4 m4 = make_float4(mx, my, mz, mw);
    reinterpret_cast<float4*>(g_avg)[i] = a4;
    reinterpret_cast<float4*>(g_max)[i] = m4;
}

// ---------------------------------------------------------------------------
// Kernel 2 (tiny, ~3 MiB traffic): cross stencil with zero padding + sigmoid.
// y3(h,w) = sum_m [ p0*y(h-1,w) + p1*y(h+1,w) + p2*y(h,w-1) + p3*y(h,w+1)
//                   - (p0+p1+p2+p3)*y(h,w) ]
// ---------------------------------------------------------------------------
__global__ void __launch_bounds__(256) stencil_kernel(const float* __restrict__ wts) {
    int i = blockIdx.x * blockDim.x + threadIdx.x;   // over B*HW = 262144
    if (i >= HX_B * HX_HW) return;
    int b  = i / HX_HW;
    int hw = i - b * HX_HW;
    int h  = hw >> 7;          // /128
    int w  = hw & 127;

    float acc = 0.f;
    #pragma unroll
    for (int m = 0; m < 2; m++) {
        const float* y = (m == 0 ? g_avg : g_max) + b * HX_HW;
        float p0 = wts[b * 8 + m * 4 + 0];
        float p1 = wts[b * 8 + m * 4 + 1];
        float p2 = wts[b * 8 + m * 4 + 2];
        float p3 = wts[b * 8 + m * 4 + 3];
        float pc = -(p0 + p1 + p2 + p3);
        float top = (h > 0)            ? y[hw - HX_W] : 0.f;
        float bot = (h < HX_H - 1)     ? y[hw + HX_W] : 0.f;
        float lft = (w > 0)            ? y[hw - 1]    : 0.f;
        float rgt = (w < HX_W - 1)     ? y[hw + 1]    : 0.f;
        acc += p0 * top + p1 * bot + p2 * lft + p3 * rgt + pc * y[hw];
    }
    g_sig[i] = 1.0f / (1.0f + __expf(-acc));
}

// ---------------------------------------------------------------------------
// Kernel 3: out = x * (1 + sigmoid(y3)), float4 streaming.
// g_sig (1 MiB) is re-read 256x per element -> stays in L2.
// ---------------------------------------------------------------------------
__global__ void __launch_bounds__(256) apply_kernel(const float4* __restrict__ x4,
                                                    float4* __restrict__ o4) {
    int i = blockIdx.x * blockDim.x + threadIdx.x;   // over B*C*HW4 = 16777216
    if (i >= HX_B * HX_C * HX_HW4) return;
    int b   = i / (HX_C * HX_HW4);
    int hw4 = i & (HX_HW4 - 1);                      // HW4 = 4096, power of 2
    float4 s = reinterpret_cast<const float4*>(g_sig)[b * HX_HW4 + hw4];
    float4 v = x4[i];
    float4 o;
    o.x = v.x * (1.0f + s.x);
    o.y = v.y * (1.0f + s.y);
    o.z = v.z * (1.0f + s.z);
    o.w = v.w * (1.0f + s.w);
    o4[i] = o;
}

extern "C" void kernel_launch(void* const* d_in, const int* in_sizes, int n_in,
                              void* d_out, int out_size) {
    const float4* x4  = (const float4*)d_in[0];
    const float*  wts = (const float*)d_in[1];
    float4*       o4  = (float4*)d_out;

    // Kernel 1: 65536 threads
    reduce_kernel<<<(HX_B * HX_HW4 + 255) / 256, 256>>>(x4);
    // Kernel 2: 262144 threads
    stencil_kernel<<<(HX_B * HX_HW + 255) / 256, 256>>>(wts);
    // Kernel 3: 16777216 threads
    apply_kernel<<<(HX_B * HX_C * HX_HW4 + 255) / 256, 256>>>(x4, o4);
}

// round 3
// speedup vs baseline: 1.0603x; 1.0603x over previous
#include <cuda_runtime.h>
#include <math.h>

#define HX_B 16
#define HX_C 256
#define HX_H 128
#define HX_W 128
#define HX_HW (HX_H * HX_W)      // 16384
#define HX_HW4 (HX_HW / 4)       // 4096

#define RED_SLICES 4             // C split 4 ways -> 4x the threads
#define RED_CPT (HX_C / RED_SLICES)  // 64 channels per thread
#define RED_PIX 64               // pixels (float4 units) per block

// scratch (device globals: allocation-free per harness rules)
__device__ float g_avg[HX_B * HX_HW];   // 1 MiB
__device__ float g_max[HX_B * HX_HW];   // 1 MiB
__device__ float g_sig[HX_B * HX_HW];   // 1 MiB

// ---------------------------------------------------------------------------
// Kernel 1: per-(b,h,w) mean & max over C=256.
// 4 threads per output float4, each reducing 64 channels; smem combine.
// tid = slice*64 + pix  -> consecutive lanes hit consecutive addresses.
// grid = 1024 blocks (was 256) -> occupancy ~4x, MLP-fed DRAM stream.
// ---------------------------------------------------------------------------
__global__ void __launch_bounds__(256) reduce_kernel(const float4* __restrict__ x4) {
    __shared__ float4 s_sum[RED_SLICES * RED_PIX];
    __shared__ float4 s_max[RED_SLICES * RED_PIX];

    int tid   = threadIdx.x;
    int pix   = tid & (RED_PIX - 1);        // 0..63
    int slice = tid >> 6;                   // 0..3
    int gpix  = blockIdx.x * RED_PIX + pix; // 0..65535 over B*HW4
    int b     = gpix / HX_HW4;
    int hw4   = gpix - b * HX_HW4;

    const float4* p = x4 + (size_t)b * HX_C * HX_HW4
                         + (size_t)(slice * RED_CPT) * HX_HW4 + hw4;

    float sx = 0.f, sy = 0.f, sz = 0.f, sw = 0.f;
    float mx = -INFINITY, my = -INFINITY, mz = -INFINITY, mw = -INFINITY;
    #pragma unroll 16
    for (int c = 0; c < RED_CPT; c++) {
        float4 v = p[(size_t)c * HX_HW4];
        sx += v.x; sy += v.y; sz += v.z; sw += v.w;
        mx = fmaxf(mx, v.x); my = fmaxf(my, v.y);
        mz = fmaxf(mz, v.z); mw = fmaxf(mw, v.w);
    }
    s_sum[tid] = make_float4(sx, sy, sz, sw);
    s_max[tid] = make_float4(mx, my, mz, mw);
    __syncthreads();

    if (slice == 0) {
        float4 a = s_sum[pix];
        float4 m = s_max[pix];
        #pragma unroll
        for (int k = 1; k < RED_SLICES; k++) {
            float4 a2 = s_sum[k * RED_PIX + pix];
            float4 m2 = s_max[k * RED_PIX + pix];
            a.x += a2.x; a.y += a2.y; a.z += a2.z; a.w += a2.w;
            m.x = fmaxf(m.x, m2.x); m.y = fmaxf(m.y, m2.y);
            m.z = fmaxf(m.z, m2.z); m.w = fmaxf(m.w, m2.w);
        }
        const float inv = 1.0f / HX_C;
        a.x *= inv; a.y *= inv; a.z *= inv; a.w *= inv;
        reinterpret_cast<float4*>(g_avg)[gpix] = a;
        reinterpret_cast<float4*>(g_max)[gpix] = m;
    }
}

// ---------------------------------------------------------------------------
// Kernel 2 (tiny, ~3 MiB traffic): cross stencil with zero padding + sigmoid.
// ---------------------------------------------------------------------------
__global__ void __launch_bounds__(256) stencil_kernel(const float* __restrict__ wts) {
    int i = blockIdx.x * blockDim.x + threadIdx.x;   // over B*HW = 262144
    if (i >= HX_B * HX_HW) return;
    int b  = i / HX_HW;
    int hw = i - b * HX_HW;
    int h  = hw >> 7;          // /128
    int w  = hw & 127;

    float acc = 0.f;
    #pragma unroll
    for (int m = 0; m < 2; m++) {
        const float* y = (m == 0 ? g_avg : g_max) + b * HX_HW;
        float p0 = wts[b * 8 + m * 4 + 0];
        float p1 = wts[b * 8 + m * 4 + 1];
        float p2 = wts[b * 8 + m * 4 + 2];
        float p3 = wts[b * 8 + m * 4 + 3];
        float pc = -(p0 + p1 + p2 + p3);
        float top = (h > 0)            ? y[hw - HX_W] : 0.f;
        float bot = (h < HX_H - 1)     ? y[hw + HX_W] : 0.f;
        float lft = (w > 0)            ? y[hw - 1]    : 0.f;
        float rgt = (w < HX_W - 1)     ? y[hw + 1]    : 0.f;
        acc += p0 * top + p1 * bot + p2 * lft + p3 * rgt + pc * y[hw];
    }
    g_sig[i] = 1.0f / (1.0f + __expf(-acc));
}

// ---------------------------------------------------------------------------
// Kernel 3: out = x * (1 + sigmoid(y3)), float4 streaming.
// g_sig (1 MiB) is re-read 256x per element -> stays in L2.
// ---------------------------------------------------------------------------
__global__ void __launch_bounds__(256) apply_kernel(const float4* __restrict__ x4,
                                                    float4* __restrict__ o4) {
    int i = blockIdx.x * blockDim.x + threadIdx.x;   // over B*C*HW4 = 16777216
    if (i >= HX_B * HX_C * HX_HW4) return;
    int b   = i / (HX_C * HX_HW4);
    int hw4 = i & (HX_HW4 - 1);                      // HW4 = 4096, power of 2
    float4 s = reinterpret_cast<const float4*>(g_sig)[b * HX_HW4 + hw4];
    float4 v = x4[i];
    float4 o;
    o.x = v.x * (1.0f + s.x);
    o.y = v.y * (1.0f + s.y);
    o.z = v.z * (1.0f + s.z);
    o.w = v.w * (1.0f + s.w);
    o4[i] = o;
}

extern "C" void kernel_launch(void* const* d_in, const int* in_sizes, int n_in,
                              void* d_out, int out_size) {
    const float4* x4  = (const float4*)d_in[0];
    const float*  wts = (const float*)d_in[1];
    float4*       o4  = (float4*)d_out;

    // Kernel 1: 262144 threads (4 per output float4)
    reduce_kernel<<<(HX_B * HX_HW4 * RED_SLICES) / 256, 256>>>(x4);
    // Kernel 2: 262144 threads
    stencil_kernel<<<(HX_B * HX_HW + 255) / 256, 256>>>(wts);
    // Kernel 3: 16777216 threads
    apply_kernel<<<(HX_B * HX_C * HX_HW4 + 255) / 256, 256>>>(x4, o4);
}